// round 6
// baseline (speedup 1.0000x reference)
#include <cuda_runtime.h>

// CenterDirectionLoss — GB300 sm_103a, 2-launch version.
//   k_hist : per-block PRIVATE 128-bin histograms (no zeroing, no global
//            atomics); last-arriving block reduces them and computes g_inv.
//   k_main : weighted |pred-gt| L1 reduction, per-block partials; last-arriving
//            block does the fixed-order final combine and writes the 5x16 output.
// Both "last block" tails are fixed-order -> deterministic across graph replays.
// Completion counters self-reset so every replay sees identical state.

#define NUM_IDS 128
#define BATCH   16
#define BPB     46          // blocks per batch -> 736 total = one full wave
#define TOTAL_BLOCKS (BATCH * BPB)
#define THREADS 256

__device__ int      g_pcounts[TOTAL_BLOCKS * NUM_IDS];  // private per-block hists
__device__ float    g_inv[BATCH * NUM_IDS];
__device__ float    g_part_sin[TOTAL_BLOCKS];
__device__ float    g_part_cos[TOTAL_BLOCKS];
__device__ unsigned g_done_hist;   // zero-init; self-resetting
__device__ unsigned g_done_main;   // zero-init; self-resetting

// ---------------------------------------------------------------------------
// Launch 1: histogram + (in last block) norm computation
// grid (BPB, BATCH), THREADS threads
// ---------------------------------------------------------------------------
__global__ void __launch_bounds__(THREADS)
k_hist(const int* __restrict__ inst, int HW) {
    __shared__ int sh[NUM_IDS];
    const int b = blockIdx.y;
    for (int i = threadIdx.x; i < NUM_IDS; i += THREADS) sh[i] = 0;
    __syncthreads();

    const int4* __restrict__ p = (const int4*)(inst + (size_t)b * HW);
    const int n4 = HW >> 2;
    for (int i = blockIdx.x * THREADS + threadIdx.x; i < n4; i += BPB * THREADS) {
        int4 v = p[i];
        atomicAdd(&sh[v.x], 1);
        atomicAdd(&sh[v.y], 1);
        atomicAdd(&sh[v.z], 1);
        atomicAdd(&sh[v.w], 1);
    }
    __syncthreads();

    // write this block's private histogram (pure overwrite — no zeroing needed)
    const int slot = b * BPB + blockIdx.x;
    for (int i = threadIdx.x; i < NUM_IDS; i += THREADS)
        g_pcounts[slot * NUM_IDS + i] = sh[i];

    // last-arriving block computes g_inv
    __threadfence();
    __shared__ bool s_last;
    if (threadIdx.x == 0)
        s_last = (atomicAdd(&g_done_hist, 1u) == TOTAL_BLOCKS - 1u);
    __syncthreads();
    if (!s_last) return;

    const int tid = threadIdx.x;
    __shared__ int   s_cnt[BATCH * NUM_IDS];   // 8 KB
    __shared__ float s_ni[THREADS];
    __shared__ float s_bg[THREADS];

    // reduce private histograms (fixed order)
    for (int bin = tid; bin < BATCH * NUM_IDS; bin += THREADS) {
        const int bb = bin >> 7;          // bin / 128
        const int id = bin & (NUM_IDS - 1);
        int sum = 0;
        #pragma unroll 2
        for (int x = 0; x < BPB; x++)
            sum += g_pcounts[(bb * BPB + x) * NUM_IDS + id];
        s_cnt[bin] = sum;
    }
    __syncthreads();

    // global scalars
    float ni = 0.f, bg = 0.f;
    for (int bin = tid; bin < BATCH * NUM_IDS; bin += THREADS) {
        const int id = bin & (NUM_IDS - 1);
        const int c  = s_cnt[bin];
        if (id == 0) bg += (float)c;
        else         ni += (c > 0) ? 1.f : 0.f;
    }
    s_ni[tid] = ni; s_bg[tid] = bg;
    __syncthreads();
    for (int s = THREADS / 2; s > 0; s >>= 1) {
        if (tid < s) { s_ni[tid] += s_ni[tid + s]; s_bg[tid] += s_bg[tid + s]; }
        __syncthreads();
    }
    const float num_inst = s_ni[0];
    const float num_bg   = s_bg[0];

    for (int bin = tid; bin < BATCH * NUM_IDS; bin += THREADS) {
        const int id = bin & (NUM_IDS - 1);
        const float c = (float)s_cnt[bin];
        const float norm = (id == 0) ? (num_bg * 2.0f)
                                     : (fmaxf(c, 1.0f) * num_inst * 2.0f);
        g_inv[bin] = 1.0f / norm;
    }

    if (tid == 0) g_done_hist = 0;   // reset for next graph replay
}

// ---------------------------------------------------------------------------
// Launch 2: weighted L1 reduction + (in last block) output write
// grid (BPB, BATCH), THREADS threads
// ---------------------------------------------------------------------------
__global__ void __launch_bounds__(THREADS)
k_main(const float* __restrict__ pred,
       const int*   __restrict__ inst,
       const float* __restrict__ gt,
       float*       __restrict__ out,
       int HW) {
    __shared__ float s_inv[NUM_IDS];
    const int b = blockIdx.y;
    for (int i = threadIdx.x; i < NUM_IDS; i += THREADS)
        s_inv[i] = g_inv[b * NUM_IDS + i];
    __syncthreads();

    const size_t HWs = (size_t)HW;
    const float4* __restrict__ ps = (const float4*)(pred + (size_t)b * 2 * HWs);
    const float4* __restrict__ pc = (const float4*)(pred + (size_t)b * 2 * HWs + HWs);
    const float4* __restrict__ gs = (const float4*)(gt + (size_t)b * 5 * HWs + 2 * HWs);
    const float4* __restrict__ gc = (const float4*)(gt + (size_t)b * 5 * HWs + 3 * HWs);
    const int4*   __restrict__ pi = (const int4*)(inst + (size_t)b * HWs);

    float as = 0.f, ac = 0.f;
    const int n4 = HW >> 2;
    for (int i = blockIdx.x * THREADS + threadIdx.x; i < n4; i += BPB * THREADS) {
        int4   id = pi[i];
        float4 a  = ps[i];
        float4 bq = pc[i];
        float4 c  = gs[i];
        float4 d  = gc[i];
        float w0 = s_inv[id.x], w1 = s_inv[id.y], w2 = s_inv[id.z], w3 = s_inv[id.w];
        as += w0 * fabsf(a.x - c.x) + w1 * fabsf(a.y - c.y)
            + w2 * fabsf(a.z - c.z) + w3 * fabsf(a.w - c.w);
        ac += w0 * fabsf(bq.x - d.x) + w1 * fabsf(bq.y - d.y)
            + w2 * fabsf(bq.z - d.z) + w3 * fabsf(bq.w - d.w);
    }

    // deterministic block reduction
    #pragma unroll
    for (int o = 16; o > 0; o >>= 1) {
        as += __shfl_down_sync(0xFFFFFFFFu, as, o);
        ac += __shfl_down_sync(0xFFFFFFFFu, ac, o);
    }
    __shared__ float rs[THREADS / 32];
    __shared__ float rc[THREADS / 32];
    const int w = threadIdx.x >> 5, l = threadIdx.x & 31;
    if (l == 0) { rs[w] = as; rc[w] = ac; }
    __syncthreads();
    if (threadIdx.x == 0) {
        float ts = 0.f, tc = 0.f;
        #pragma unroll
        for (int i = 0; i < THREADS / 32; i++) { ts += rs[i]; tc += rc[i]; }
        const int slot = b * BPB + blockIdx.x;
        g_part_sin[slot] = ts;
        g_part_cos[slot] = tc;
    }

    // last-arriving block writes the output (fixed-order combine)
    __threadfence();
    __shared__ bool s_last;
    if (threadIdx.x == 0)
        s_last = (atomicAdd(&g_done_main, 1u) == TOTAL_BLOCKS - 1u);
    __syncthreads();
    if (!s_last) return;

    const int bb = threadIdx.x;
    if (bb < BATCH) {
        float s = 0.f, c = 0.f;
        #pragma unroll 2
        for (int i = 0; i < BPB; i++) {
            s += g_part_sin[bb * BPB + i];
            c += g_part_cos[bb * BPB + i];
        }
        const float tot = s + c;
        out[0 * BATCH + bb] = tot;   // loss
        out[1 * BATCH + bb] = tot;   // loss_direction_total
        out[2 * BATCH + bb] = 0.0f;  // loss_centers
        out[3 * BATCH + bb] = s;     // loss_sin
        out[4 * BATCH + bb] = c;     // loss_cos
    }
    if (threadIdx.x == 0) g_done_main = 0;   // reset for next graph replay
}

extern "C" void kernel_launch(void* const* d_in, const int* in_sizes, int n_in,
                              void* d_out, int out_size) {
    const float* pred = (const float*)d_in[0];   // (16, 2, 768, 768) f32
    const int*   inst = (const int*)d_in[1];     // (16, 768, 768) i32
    // d_in[2] = labels (unused: W_FG == W_BG == 1.0)
    const float* gt   = (const float*)d_in[3];   // (16, 5, 768, 768) f32
    float*       out  = (float*)d_out;           // 5 x 16 f32

    const int HW = in_sizes[1] / BATCH;

    dim3 grid(BPB, BATCH);
    k_hist<<<grid, THREADS>>>(inst, HW);
    k_main<<<grid, THREADS>>>(pred, inst, gt, out, HW);
}

// round 7
// speedup vs baseline: 1.4716x; 1.4716x over previous
#include <cuda_runtime.h>

// CenterDirectionLoss — GB300 sm_103a, 2-launch version (v3).
//   k_hist : smem 128-bin histogram per block, global atomicAdd into g_counts;
//            last-arriving block computes g_inv and ZEROES g_counts for the
//            next graph replay (no zeroing kernel, no big serial gather).
//   k_main : weighted |pred-gt| L1 reduction (BPB=74, R1-measured-best grid),
//            per-block partials; last-arriving block does the fixed-order
//            combine and writes the 5x16 output.
// All tails are fixed-order -> deterministic across graph replays.
// g_counts and the done-counters self-reset each replay.

#define NUM_IDS 128
#define BATCH   16
#define BPB     74          // blocks per batch (R1-measured best for k_main)
#define TOTAL_BLOCKS (BATCH * BPB)
#define THREADS 256

__device__ int      g_counts[BATCH * NUM_IDS];   // zero-init; self-resetting
__device__ float    g_inv[BATCH * NUM_IDS];
__device__ float    g_part_sin[TOTAL_BLOCKS];
__device__ float    g_part_cos[TOTAL_BLOCKS];
__device__ unsigned g_done_hist;   // zero-init; self-resetting
__device__ unsigned g_done_main;   // zero-init; self-resetting

// ---------------------------------------------------------------------------
// Launch 1: histogram + (in last block) norm computation + counts reset
// grid (BPB, BATCH), THREADS threads
// ---------------------------------------------------------------------------
__global__ void __launch_bounds__(THREADS)
k_hist(const int* __restrict__ inst, int HW) {
    __shared__ int sh[NUM_IDS];
    const int b = blockIdx.y;
    for (int i = threadIdx.x; i < NUM_IDS; i += THREADS) sh[i] = 0;
    __syncthreads();

    const int4* __restrict__ p = (const int4*)(inst + (size_t)b * HW);
    const int n4 = HW >> 2;
    for (int i = blockIdx.x * THREADS + threadIdx.x; i < n4; i += BPB * THREADS) {
        int4 v = p[i];
        atomicAdd(&sh[v.x], 1);
        atomicAdd(&sh[v.y], 1);
        atomicAdd(&sh[v.z], 1);
        atomicAdd(&sh[v.w], 1);
    }
    __syncthreads();

    // merge block histogram into the global one (<=128 atomics per block)
    for (int i = threadIdx.x; i < NUM_IDS; i += THREADS) {
        int c = sh[i];
        if (c) atomicAdd(&g_counts[b * NUM_IDS + i], c);
    }

    // last-arriving block computes g_inv, then zeroes g_counts for next replay
    __threadfence();
    __shared__ bool s_last;
    if (threadIdx.x == 0)
        s_last = (atomicAdd(&g_done_hist, 1u) == TOTAL_BLOCKS - 1u);
    __syncthreads();
    if (!s_last) return;

    const int tid = threadIdx.x;
    __shared__ int   s_cnt[BATCH * NUM_IDS];   // 8 KB
    __shared__ float s_ni[THREADS];
    __shared__ float s_bg[THREADS];

    // read final counts (L2 loads, bypass L1 — atomics completed in L2)
    for (int bin = tid; bin < BATCH * NUM_IDS; bin += THREADS)
        s_cnt[bin] = __ldcg(&g_counts[bin]);
    __syncthreads();

    // global scalars
    float ni = 0.f, bg = 0.f;
    for (int bin = tid; bin < BATCH * NUM_IDS; bin += THREADS) {
        const int id = bin & (NUM_IDS - 1);
        const int c  = s_cnt[bin];
        if (id == 0) bg += (float)c;
        else         ni += (c > 0) ? 1.f : 0.f;
    }
    s_ni[tid] = ni; s_bg[tid] = bg;
    __syncthreads();
    for (int s = THREADS / 2; s > 0; s >>= 1) {
        if (tid < s) { s_ni[tid] += s_ni[tid + s]; s_bg[tid] += s_bg[tid + s]; }
        __syncthreads();
    }
    const float num_inst = s_ni[0];
    const float num_bg   = s_bg[0];

    for (int bin = tid; bin < BATCH * NUM_IDS; bin += THREADS) {
        const int id = bin & (NUM_IDS - 1);
        const float c = (float)s_cnt[bin];
        const float norm = (id == 0) ? (num_bg * 2.0f)
                                     : (fmaxf(c, 1.0f) * num_inst * 2.0f);
        g_inv[bin] = 1.0f / norm;
        g_counts[bin] = 0;               // reset for next graph replay
    }

    if (tid == 0) g_done_hist = 0;       // reset for next graph replay
}

// ---------------------------------------------------------------------------
// Launch 2: weighted L1 reduction + (in last block) output write
// grid (BPB, BATCH), THREADS threads
// ---------------------------------------------------------------------------
__global__ void __launch_bounds__(THREADS)
k_main(const float* __restrict__ pred,
       const int*   __restrict__ inst,
       const float* __restrict__ gt,
       float*       __restrict__ out,
       int HW) {
    __shared__ float s_inv[NUM_IDS];
    const int b = blockIdx.y;
    for (int i = threadIdx.x; i < NUM_IDS; i += THREADS)
        s_inv[i] = g_inv[b * NUM_IDS + i];
    __syncthreads();

    const size_t HWs = (size_t)HW;
    const float4* __restrict__ ps = (const float4*)(pred + (size_t)b * 2 * HWs);
    const float4* __restrict__ pc = (const float4*)(pred + (size_t)b * 2 * HWs + HWs);
    const float4* __restrict__ gs = (const float4*)(gt + (size_t)b * 5 * HWs + 2 * HWs);
    const float4* __restrict__ gc = (const float4*)(gt + (size_t)b * 5 * HWs + 3 * HWs);
    const int4*   __restrict__ pi = (const int4*)(inst + (size_t)b * HWs);

    float as = 0.f, ac = 0.f;
    const int n4 = HW >> 2;
    for (int i = blockIdx.x * THREADS + threadIdx.x; i < n4; i += BPB * THREADS) {
        int4   id = pi[i];
        float4 a  = ps[i];
        float4 bq = pc[i];
        float4 c  = gs[i];
        float4 d  = gc[i];
        float w0 = s_inv[id.x], w1 = s_inv[id.y], w2 = s_inv[id.z], w3 = s_inv[id.w];
        as += w0 * fabsf(a.x - c.x) + w1 * fabsf(a.y - c.y)
            + w2 * fabsf(a.z - c.z) + w3 * fabsf(a.w - c.w);
        ac += w0 * fabsf(bq.x - d.x) + w1 * fabsf(bq.y - d.y)
            + w2 * fabsf(bq.z - d.z) + w3 * fabsf(bq.w - d.w);
    }

    // deterministic block reduction
    #pragma unroll
    for (int o = 16; o > 0; o >>= 1) {
        as += __shfl_down_sync(0xFFFFFFFFu, as, o);
        ac += __shfl_down_sync(0xFFFFFFFFu, ac, o);
    }
    __shared__ float rs[THREADS / 32];
    __shared__ float rc[THREADS / 32];
    const int w = threadIdx.x >> 5, l = threadIdx.x & 31;
    if (l == 0) { rs[w] = as; rc[w] = ac; }
    __syncthreads();
    if (threadIdx.x == 0) {
        float ts = 0.f, tc = 0.f;
        #pragma unroll
        for (int i = 0; i < THREADS / 32; i++) { ts += rs[i]; tc += rc[i]; }
        const int slot = b * BPB + blockIdx.x;
        g_part_sin[slot] = ts;
        g_part_cos[slot] = tc;
    }

    // last-arriving block writes the output (fixed-order combine)
    __threadfence();
    __shared__ bool s_last;
    if (threadIdx.x == 0)
        s_last = (atomicAdd(&g_done_main, 1u) == TOTAL_BLOCKS - 1u);
    __syncthreads();
    if (!s_last) return;

    const int bb = threadIdx.x;
    if (bb < BATCH) {
        float s = 0.f, c = 0.f;
        #pragma unroll 2
        for (int i = 0; i < BPB; i++) {
            s += __ldcg(&g_part_sin[bb * BPB + i]);
            c += __ldcg(&g_part_cos[bb * BPB + i]);
        }
        const float tot = s + c;
        out[0 * BATCH + bb] = tot;   // loss
        out[1 * BATCH + bb] = tot;   // loss_direction_total
        out[2 * BATCH + bb] = 0.0f;  // loss_centers
        out[3 * BATCH + bb] = s;     // loss_sin
        out[4 * BATCH + bb] = c;     // loss_cos
    }
    if (threadIdx.x == 0) g_done_main = 0;   // reset for next graph replay
}

extern "C" void kernel_launch(void* const* d_in, const int* in_sizes, int n_in,
                              void* d_out, int out_size) {
    const float* pred = (const float*)d_in[0];   // (16, 2, 768, 768) f32
    const int*   inst = (const int*)d_in[1];     // (16, 768, 768) i32
    // d_in[2] = labels (unused: W_FG == W_BG == 1.0)
    const float* gt   = (const float*)d_in[3];   // (16, 5, 768, 768) f32
    float*       out  = (float*)d_out;           // 5 x 16 f32

    const int HW = in_sizes[1] / BATCH;

    dim3 grid(BPB, BATCH);
    k_hist<<<grid, THREADS>>>(inst, HW);
    k_main<<<grid, THREADS>>>(pred, inst, gt, out, HW);
}

// round 11
// speedup vs baseline: 1.5138x; 1.0287x over previous
#include <cuda_runtime.h>

// CenterDirectionLoss — GB300 sm_103a, 2-launch version (v4).
//   k_hist : smem 128-bin histogram per block, global atomicAdd into g_counts;
//            last-arriving block computes g_inv and zeroes g_counts.
//   k_main : weighted |pred-gt| L1 reduction, unroll-2 (10 independent 16B
//            loads/iter for MLP); tail fence+atomic executed by thread 0 ONLY
//            (it is the sole writer of the partials); last-arriving block
//            combines in fixed order and writes the 5x16 output.
// All tails fixed-order -> deterministic across graph replays; counters and
// g_counts self-reset each replay.

#define NUM_IDS 128
#define BATCH   16
#define BPB     74
#define TOTAL_BLOCKS (BATCH * BPB)
#define THREADS 256

__device__ int      g_counts[BATCH * NUM_IDS];   // zero-init; self-resetting
__device__ float    g_inv[BATCH * NUM_IDS];
__device__ float    g_part_sin[TOTAL_BLOCKS];
__device__ float    g_part_cos[TOTAL_BLOCKS];
__device__ unsigned g_done_hist;   // zero-init; self-resetting
__device__ unsigned g_done_main;   // zero-init; self-resetting

// ---------------------------------------------------------------------------
// Launch 1: histogram + (in last block) norm computation + counts reset
// ---------------------------------------------------------------------------
__global__ void __launch_bounds__(THREADS)
k_hist(const int* __restrict__ inst, int HW) {
    __shared__ int sh[NUM_IDS];
    const int b = blockIdx.y;
    for (int i = threadIdx.x; i < NUM_IDS; i += THREADS) sh[i] = 0;
    __syncthreads();

    const int4* __restrict__ p = (const int4*)(inst + (size_t)b * HW);
    const int n4 = HW >> 2;
    for (int i = blockIdx.x * THREADS + threadIdx.x; i < n4; i += BPB * THREADS) {
        int4 v = p[i];
        atomicAdd(&sh[v.x], 1);
        atomicAdd(&sh[v.y], 1);
        atomicAdd(&sh[v.z], 1);
        atomicAdd(&sh[v.w], 1);
    }
    __syncthreads();

    for (int i = threadIdx.x; i < NUM_IDS; i += THREADS) {
        int c = sh[i];
        if (c) atomicAdd(&g_counts[b * NUM_IDS + i], c);
    }

    __threadfence();   // order this block's histogram atomics before done-count
    __shared__ bool s_last;
    if (threadIdx.x == 0)
        s_last = (atomicAdd(&g_done_hist, 1u) == TOTAL_BLOCKS - 1u);
    __syncthreads();
    if (!s_last) return;

    const int tid = threadIdx.x;
    __shared__ int   s_cnt[BATCH * NUM_IDS];
    __shared__ float s_ni[THREADS];
    __shared__ float s_bg[THREADS];

    for (int bin = tid; bin < BATCH * NUM_IDS; bin += THREADS)
        s_cnt[bin] = __ldcg(&g_counts[bin]);
    __syncthreads();

    float ni = 0.f, bg = 0.f;
    for (int bin = tid; bin < BATCH * NUM_IDS; bin += THREADS) {
        const int id = bin & (NUM_IDS - 1);
        const int c  = s_cnt[bin];
        if (id == 0) bg += (float)c;
        else         ni += (c > 0) ? 1.f : 0.f;
    }
    s_ni[tid] = ni; s_bg[tid] = bg;
    __syncthreads();
    for (int s = THREADS / 2; s > 0; s >>= 1) {
        if (tid < s) { s_ni[tid] += s_ni[tid + s]; s_bg[tid] += s_bg[tid + s]; }
        __syncthreads();
    }
    const float num_inst = s_ni[0];
    const float num_bg   = s_bg[0];

    for (int bin = tid; bin < BATCH * NUM_IDS; bin += THREADS) {
        const int id = bin & (NUM_IDS - 1);
        const float c = (float)s_cnt[bin];
        const float norm = (id == 0) ? (num_bg * 2.0f)
                                     : (fmaxf(c, 1.0f) * num_inst * 2.0f);
        g_inv[bin] = 1.0f / norm;
        g_counts[bin] = 0;               // reset for next graph replay
    }
    if (tid == 0) g_done_hist = 0;       // reset for next graph replay
}

// ---------------------------------------------------------------------------
// Launch 2: weighted L1 reduction (unroll-2) + (in last block) output write
// ---------------------------------------------------------------------------
__global__ void __launch_bounds__(THREADS)
k_main(const float* __restrict__ pred,
       const int*   __restrict__ inst,
       const float* __restrict__ gt,
       float*       __restrict__ out,
       int HW) {
    __shared__ float s_inv[NUM_IDS];
    const int b = blockIdx.y;
    for (int i = threadIdx.x; i < NUM_IDS; i += THREADS)
        s_inv[i] = g_inv[b * NUM_IDS + i];
    __syncthreads();

    const size_t HWs = (size_t)HW;
    const float4* __restrict__ ps = (const float4*)(pred + (size_t)b * 2 * HWs);
    const float4* __restrict__ pc = (const float4*)(pred + (size_t)b * 2 * HWs + HWs);
    const float4* __restrict__ gs = (const float4*)(gt + (size_t)b * 5 * HWs + 2 * HWs);
    const float4* __restrict__ gc = (const float4*)(gt + (size_t)b * 5 * HWs + 3 * HWs);
    const int4*   __restrict__ pi = (const int4*)(inst + (size_t)b * HWs);

    float as = 0.f, ac = 0.f;
    const int n8     = HW >> 3;          // pairs of vec4
    const int stride = BPB * THREADS;
    for (int i = blockIdx.x * THREADS + threadIdx.x; i < n8; i += stride) {
        const int j = 2 * i;
        // 10 independent 16B loads batched per iteration (MLP)
        int4   id0 = pi[j],     id1 = pi[j + 1];
        float4 a0  = ps[j],     a1  = ps[j + 1];
        float4 b0  = pc[j],     b1  = pc[j + 1];
        float4 c0  = gs[j],     c1  = gs[j + 1];
        float4 d0  = gc[j],     d1  = gc[j + 1];

        float w00 = s_inv[id0.x], w01 = s_inv[id0.y], w02 = s_inv[id0.z], w03 = s_inv[id0.w];
        float w10 = s_inv[id1.x], w11 = s_inv[id1.y], w12 = s_inv[id1.z], w13 = s_inv[id1.w];

        as += w00 * fabsf(a0.x - c0.x) + w01 * fabsf(a0.y - c0.y)
            + w02 * fabsf(a0.z - c0.z) + w03 * fabsf(a0.w - c0.w);
        as += w10 * fabsf(a1.x - c1.x) + w11 * fabsf(a1.y - c1.y)
            + w12 * fabsf(a1.z - c1.z) + w13 * fabsf(a1.w - c1.w);
        ac += w00 * fabsf(b0.x - d0.x) + w01 * fabsf(b0.y - d0.y)
            + w02 * fabsf(b0.z - d0.z) + w03 * fabsf(b0.w - d0.w);
        ac += w10 * fabsf(b1.x - d1.x) + w11 * fabsf(b1.y - d1.y)
            + w12 * fabsf(b1.z - d1.z) + w13 * fabsf(b1.w - d1.w);
    }

    // deterministic block reduction
    #pragma unroll
    for (int o = 16; o > 0; o >>= 1) {
        as += __shfl_down_sync(0xFFFFFFFFu, as, o);
        ac += __shfl_down_sync(0xFFFFFFFFu, ac, o);
    }
    __shared__ float rs[THREADS / 32];
    __shared__ float rc[THREADS / 32];
    const int w = threadIdx.x >> 5, l = threadIdx.x & 31;
    if (l == 0) { rs[w] = as; rc[w] = ac; }
    __syncthreads();

    // thread 0 is the SOLE writer of the partials -> only it needs the fence
    __shared__ bool s_last;
    if (threadIdx.x == 0) {
        float ts = 0.f, tc = 0.f;
        #pragma unroll
        for (int i = 0; i < THREADS / 32; i++) { ts += rs[i]; tc += rc[i]; }
        const int slot = b * BPB + blockIdx.x;
        g_part_sin[slot] = ts;
        g_part_cos[slot] = tc;
        __threadfence();
        s_last = (atomicAdd(&g_done_main, 1u) == TOTAL_BLOCKS - 1u);
    }
    __syncthreads();
    if (!s_last) return;

    const int bb = threadIdx.x;
    if (bb < BATCH) {
        float s = 0.f, c = 0.f;
        #pragma unroll 2
        for (int i = 0; i < BPB; i++) {
            s += __ldcg(&g_part_sin[bb * BPB + i]);
            c += __ldcg(&g_part_cos[bb * BPB + i]);
        }
        const float tot = s + c;
        out[0 * BATCH + bb] = tot;   // loss
        out[1 * BATCH + bb] = tot;   // loss_direction_total
        out[2 * BATCH + bb] = 0.0f;  // loss_centers
        out[3 * BATCH + bb] = s;     // loss_sin
        out[4 * BATCH + bb] = c;     // loss_cos
    }
    if (threadIdx.x == 0) g_done_main = 0;   // reset for next graph replay
}

extern "C" void kernel_launch(void* const* d_in, const int* in_sizes, int n_in,
                              void* d_out, int out_size) {
    const float* pred = (const float*)d_in[0];   // (16, 2, 768, 768) f32
    const int*   inst = (const int*)d_in[1];     // (16, 768, 768) i32
    // d_in[2] = labels (unused: W_FG == W_BG == 1.0)
    const float* gt   = (const float*)d_in[3];   // (16, 5, 768, 768) f32
    float*       out  = (float*)d_out;           // 5 x 16 f32

    const int HW = in_sizes[1] / BATCH;

    dim3 grid(BPB, BATCH);
    k_hist<<<grid, THREADS>>>(inst, HW);
    k_main<<<grid, THREADS>>>(pred, inst, gt, out, HW);
}

// round 14
// speedup vs baseline: 1.6327x; 1.0785x over previous
#include <cuda_runtime.h>

// CenterDirectionLoss — GB300 sm_103a, v5: 3 launches.
//   k_hist : smem 128-bin histogram + global atomicAdd; last-arriving block
//            computes g_inv and zeroes g_counts (fused norm, measured cheap).
//   k_main : EXACT R1 replica of the weighted |pred-gt| L1 mainloop — no fused
//            epilogue, no extra params; per-block partials only. (R1 measured
//            33.4us @73% DRAM; every fused-tail variant measured 38-47us.)
//   k_out  : 1-block fixed-order combine -> 5x16 outputs.
// Deterministic: int atomics only affect counts; all float sums fixed-order.

#define NUM_IDS 128
#define BATCH   16
#define BPB     74
#define TOTAL_BLOCKS (BATCH * BPB)
#define THREADS 256

__device__ int      g_counts[BATCH * NUM_IDS];   // zero-init; self-resetting
__device__ float    g_inv[BATCH * NUM_IDS];
__device__ float    g_part_sin[TOTAL_BLOCKS];
__device__ float    g_part_cos[TOTAL_BLOCKS];
__device__ unsigned g_done_hist;                 // zero-init; self-resetting

// ---------------------------------------------------------------------------
// Launch 1: histogram + (in last block) norm computation + counts reset
// grid (BPB, BATCH), THREADS threads
// ---------------------------------------------------------------------------
__global__ void __launch_bounds__(THREADS)
k_hist(const int* __restrict__ inst, int HW) {
    __shared__ int sh[NUM_IDS];
    const int b = blockIdx.y;
    for (int i = threadIdx.x; i < NUM_IDS; i += THREADS) sh[i] = 0;
    __syncthreads();

    const int4* __restrict__ p = (const int4*)(inst + (size_t)b * HW);
    const int n4 = HW >> 2;
    for (int i = blockIdx.x * THREADS + threadIdx.x; i < n4; i += BPB * THREADS) {
        int4 v = p[i];
        atomicAdd(&sh[v.x], 1);
        atomicAdd(&sh[v.y], 1);
        atomicAdd(&sh[v.z], 1);
        atomicAdd(&sh[v.w], 1);
    }
    __syncthreads();

    for (int i = threadIdx.x; i < NUM_IDS; i += THREADS) {
        int c = sh[i];
        if (c) atomicAdd(&g_counts[b * NUM_IDS + i], c);
    }

    __threadfence();   // order this block's histogram atomics before done-count
    __shared__ bool s_last;
    if (threadIdx.x == 0)
        s_last = (atomicAdd(&g_done_hist, 1u) == TOTAL_BLOCKS - 1u);
    __syncthreads();
    if (!s_last) return;

    const int tid = threadIdx.x;
    __shared__ int   s_cnt[BATCH * NUM_IDS];
    __shared__ float s_ni[THREADS];
    __shared__ float s_bg[THREADS];

    for (int bin = tid; bin < BATCH * NUM_IDS; bin += THREADS)
        s_cnt[bin] = __ldcg(&g_counts[bin]);
    __syncthreads();

    float ni = 0.f, bg = 0.f;
    for (int bin = tid; bin < BATCH * NUM_IDS; bin += THREADS) {
        const int id = bin & (NUM_IDS - 1);
        const int c  = s_cnt[bin];
        if (id == 0) bg += (float)c;
        else         ni += (c > 0) ? 1.f : 0.f;
    }
    s_ni[tid] = ni; s_bg[tid] = bg;
    __syncthreads();
    for (int s = THREADS / 2; s > 0; s >>= 1) {
        if (tid < s) { s_ni[tid] += s_ni[tid + s]; s_bg[tid] += s_bg[tid + s]; }
        __syncthreads();
    }
    const float num_inst = s_ni[0];
    const float num_bg   = s_bg[0];

    for (int bin = tid; bin < BATCH * NUM_IDS; bin += THREADS) {
        const int id = bin & (NUM_IDS - 1);
        const float c = (float)s_cnt[bin];
        const float norm = (id == 0) ? (num_bg * 2.0f)
                                     : (fmaxf(c, 1.0f) * num_inst * 2.0f);
        g_inv[bin] = 1.0f / norm;
        g_counts[bin] = 0;               // reset for next graph replay
    }
    if (tid == 0) g_done_hist = 0;       // reset for next graph replay
}

// ---------------------------------------------------------------------------
// Launch 2: weighted L1 reduction — EXACT R1 structure (no epilogue fusion)
// grid (BPB, BATCH), THREADS threads
// ---------------------------------------------------------------------------
__global__ void __launch_bounds__(THREADS)
k_main(const float* __restrict__ pred,
       const int*   __restrict__ inst,
       const float* __restrict__ gt,
       int HW) {
    __shared__ float s_inv[NUM_IDS];
    const int b = blockIdx.y;
    for (int i = threadIdx.x; i < NUM_IDS; i += blockDim.x)
        s_inv[i] = g_inv[b * NUM_IDS + i];
    __syncthreads();

    const size_t HWs = (size_t)HW;
    const float4* __restrict__ ps = (const float4*)(pred + (size_t)b * 2 * HWs);
    const float4* __restrict__ pc = (const float4*)(pred + (size_t)b * 2 * HWs + HWs);
    const float4* __restrict__ gs = (const float4*)(gt + (size_t)b * 5 * HWs + 2 * HWs);
    const float4* __restrict__ gc = (const float4*)(gt + (size_t)b * 5 * HWs + 3 * HWs);
    const int4*   __restrict__ pi = (const int4*)(inst + (size_t)b * HWs);

    float as = 0.f, ac = 0.f;
    const int n4 = HW >> 2;
    for (int i = blockIdx.x * blockDim.x + threadIdx.x; i < n4;
         i += gridDim.x * blockDim.x) {
        int4   id = pi[i];
        float4 a  = ps[i];
        float4 bq = pc[i];
        float4 c  = gs[i];
        float4 d  = gc[i];
        float w0 = s_inv[id.x], w1 = s_inv[id.y], w2 = s_inv[id.z], w3 = s_inv[id.w];
        as += w0 * fabsf(a.x - c.x) + w1 * fabsf(a.y - c.y)
            + w2 * fabsf(a.z - c.z) + w3 * fabsf(a.w - c.w);
        ac += w0 * fabsf(bq.x - d.x) + w1 * fabsf(bq.y - d.y)
            + w2 * fabsf(bq.z - d.z) + w3 * fabsf(bq.w - d.w);
    }

    // deterministic block reduction: warp shuffle -> smem -> thread 0
    #pragma unroll
    for (int o = 16; o > 0; o >>= 1) {
        as += __shfl_down_sync(0xFFFFFFFFu, as, o);
        ac += __shfl_down_sync(0xFFFFFFFFu, ac, o);
    }
    __shared__ float rs[THREADS / 32];
    __shared__ float rc[THREADS / 32];
    const int w = threadIdx.x >> 5, l = threadIdx.x & 31;
    if (l == 0) { rs[w] = as; rc[w] = ac; }
    __syncthreads();
    if (threadIdx.x == 0) {
        float ts = 0.f, tc = 0.f;
        #pragma unroll
        for (int i = 0; i < THREADS / 32; i++) { ts += rs[i]; tc += rc[i]; }
        g_part_sin[b * BPB + blockIdx.x] = ts;
        g_part_cos[b * BPB + blockIdx.x] = tc;
    }
}

// ---------------------------------------------------------------------------
// Launch 3: one block, 32 threads — fixed-order final sums + output layout
// ---------------------------------------------------------------------------
__global__ void k_out(float* __restrict__ out) {
    const int b = threadIdx.x;
    if (b < BATCH) {
        float s = 0.f, c = 0.f;
        #pragma unroll 4
        for (int i = 0; i < BPB; i++) {
            s += g_part_sin[b * BPB + i];
            c += g_part_cos[b * BPB + i];
        }
        const float tot = s + c;
        out[0 * BATCH + b] = tot;   // loss
        out[1 * BATCH + b] = tot;   // loss_direction_total
        out[2 * BATCH + b] = 0.0f;  // loss_centers
        out[3 * BATCH + b] = s;     // loss_sin
        out[4 * BATCH + b] = c;     // loss_cos
    }
}

extern "C" void kernel_launch(void* const* d_in, const int* in_sizes, int n_in,
                              void* d_out, int out_size) {
    const float* pred = (const float*)d_in[0];   // (16, 2, 768, 768) f32
    const int*   inst = (const int*)d_in[1];     // (16, 768, 768) i32
    // d_in[2] = labels (unused: W_FG == W_BG == 1.0)
    const float* gt   = (const float*)d_in[3];   // (16, 5, 768, 768) f32
    float*       out  = (float*)d_out;           // 5 x 16 f32

    const int HW = in_sizes[1] / BATCH;

    dim3 grid(BPB, BATCH);
    k_hist<<<grid, THREADS>>>(inst, HW);
    k_main<<<grid, THREADS>>>(pred, inst, gt, HW);
    k_out<<<1, 32>>>(out);
}